// round 6
// baseline (speedup 1.0000x reference)
#include <cuda_runtime.h>
#include <math.h>
#include <stdint.h>

#define D_MODEL 1024
#define D_INNER 2048
#define D_STATE 16
#define DT_RANK 64
#define BATCH   2
#define SEQLEN  2048
#define BL      (BATCH * SEQLEN)   // 4096 rows

// ---------------- scratch (static device globals; no allocation allowed) ---
// Packed operand layout, per 128(row)x16(k) tile (2048 floats = 8KB):
//   A-style:  addr = (ks*8 + i16)*128 + row8*16 + kq*4 + sub8 + 2*khalf
//   B-style:  addr = (ks*8 + jp )*128 + n8*16  + kq*4 + jodd*2 + khalf
// where ks=(k>>3)&1, khalf=(k>>2)&1, kq=k&3, i16=(m>>4)&7, sub8=(m>>3)&1,
// row8=m&7, jp=(n>>4)&7, jodd=(n>>3)&1, n8=n&7.
// Tiles ordered [m/128][k/16] (A) or [n/128][k/16] (B).
__device__ float g_hsP[(size_t)BL * D_MODEL];              // 16 MB packed A (GEMM1)
__device__ float g_winP[(size_t)D_MODEL * 2 * D_INNER];    // 16 MB packed B (GEMM1)
__device__ float g_wdtP[(size_t)DT_RANK * D_INNER];        // 0.5 MB packed B (delta)
__device__ float g_woutP[(size_t)D_INNER * D_MODEL];       // 8 MB packed B (out)
__device__ float g_xdblP[(size_t)BL * DT_RANK];            // 1 MB packed A (delta)
__device__ float g_outpreP[(size_t)BL * D_INNER];          // 32 MB packed A (out)
__device__ float g_bc[(size_t)BL * 32];                    // 0.5 MB B/C for scan
__device__ float g_xraw[(size_t)BL * D_INNER];             // 32 MB x pre-conv
__device__ float g_x[(size_t)BL * D_INNER];                // 32 MB x post conv+silu
__device__ float g_zs[(size_t)BL * D_INNER];               // 32 MB silu(z)
__device__ float g_delta[(size_t)BL * D_INNER];            // 32 MB softplus(dt)

__device__ __forceinline__ float ex2f(float x) {
    float y; asm("ex2.approx.f32 %0, %1;" : "=f"(y) : "f"(x)); return y;
}
__device__ __forceinline__ float f2tf_f(float x) {
    unsigned r; asm("cvt.rna.tf32.f32 %0, %1;" : "=r"(r) : "f"(x));
    return __uint_as_float(r);
}

// ---------------- pack A: [M,K] row-major -> fragment-packed, tf32-rounded --
__global__ __launch_bounds__(256) void pack_a(
    const float* __restrict__ in, float* __restrict__ out, int M, int K)
{
    const int nkt = K >> 4;
    const int tid = blockIdx.x * 256 + threadIdx.x;   // = row * nkt + kt
    const int row = tid / nkt;
    const int kt  = tid - row * nkt;
    if (row >= M) return;

    const float4* src = (const float4*)(in + (size_t)row * K + kt * 16);
    float4 v0 = src[0], v1 = src[1], v2 = src[2], v3 = src[3];

    float* dst = out + ((size_t)(row >> 7) * nkt + kt) * 2048
               + ((row >> 4) & 7) * 128 + (row & 7) * 16 + ((row >> 3) & 1);
    // ks=0
    dst[0]  = f2tf_f(v0.x); dst[4]  = f2tf_f(v0.y);
    dst[8]  = f2tf_f(v0.z); dst[12] = f2tf_f(v0.w);
    dst[2]  = f2tf_f(v1.x); dst[6]  = f2tf_f(v1.y);
    dst[10] = f2tf_f(v1.z); dst[14] = f2tf_f(v1.w);
    // ks=1
    dst[1024 + 0]  = f2tf_f(v2.x); dst[1024 + 4]  = f2tf_f(v2.y);
    dst[1024 + 8]  = f2tf_f(v2.z); dst[1024 + 12] = f2tf_f(v2.w);
    dst[1024 + 2]  = f2tf_f(v3.x); dst[1024 + 6]  = f2tf_f(v3.y);
    dst[1024 + 10] = f2tf_f(v3.z); dst[1024 + 14] = f2tf_f(v3.w);
}

// ---------------- pack B: W[K,N] row-major -> Bt fragment-packed ------------
__global__ __launch_bounds__(256) void pack_b(
    const float* __restrict__ W, float* __restrict__ out, int K, int N)
{
    const int nkt = K >> 4;
    const int tid = blockIdx.x * 256 + threadIdx.x;   // = kt * N + n
    const int kt  = tid / N;
    const int n   = tid - kt * N;
    if (kt >= nkt) return;

    float* dst = out + ((size_t)(n >> 7) * nkt + kt) * 2048
               + ((n >> 4) & 7) * 128 + (n & 7) * 16 + ((n >> 3) & 1) * 2;
    const float* src = W + (size_t)(kt * 16) * N + n;
#pragma unroll
    for (int e = 0; e < 16; ++e) {
        const int ks = e >> 3, khalf = (e >> 2) & 1, kq = e & 3;
        dst[ks * 1024 + kq * 4 + khalf] = f2tf_f(src[(size_t)e * N]);
    }
}

// ---------------- TF32 mma GEMM on fragment-packed operands -----------------
// C[M,N] = A @ B^T.  Ap: packed [M/128][nkt] tiles; Bp: packed [N/128][nkt].
// 128x128 CTA tile, 256 threads (8 warps 2x4), warp 64x32, m16n8k8, double buf.
// EPI 0: plain. 1: softplus(acc+bias[col]). 2: even->C, silu(odd)->aux (ch=col/2).
template <int EPI>
__global__ __launch_bounds__(256) void mma_gemm_p(
    const float* __restrict__ Ap, const float* __restrict__ Bp,
    float* __restrict__ C, const float* __restrict__ bias, float* __restrict__ aux,
    int nkt, int ldc)
{
    __shared__ float4 As[2][512];
    __shared__ float4 Bs[2][512];

    const int tid  = threadIdx.x;
    const int warp = tid >> 5;
    const int lane = tid & 31;
    const int brow = blockIdx.y * 128;
    const int bcol = blockIdx.x * 128;

    const int wm   = (warp >> 2) * 64;
    const int wn   = (warp & 3) * 32;
    const int wm16 = (warp >> 2) * 4;   // i16 base
    const int wjp  = (warp & 3) * 2;    // jpair base

    const float4* Ag = (const float4*)Ap + (size_t)blockIdx.y * nkt * 512;
    const float4* Bg = (const float4*)Bp + (size_t)blockIdx.x * nkt * 512;

    float acc[4][4][4];
#pragma unroll
    for (int i = 0; i < 4; ++i)
#pragma unroll
        for (int j = 0; j < 4; ++j)
#pragma unroll
            for (int q = 0; q < 4; ++q) acc[i][j][q] = 0.f;

    // prologue: tile 0 -> buffer 0
    {
        float4 a0 = Ag[tid * 2], a1 = Ag[tid * 2 + 1];
        float4 b0 = Bg[tid * 2], b1 = Bg[tid * 2 + 1];
        As[0][tid * 2] = a0; As[0][tid * 2 + 1] = a1;
        Bs[0][tid * 2] = b0; Bs[0][tid * 2 + 1] = b1;
    }
    __syncthreads();

    for (int kt = 0; kt < nkt; ++kt) {
        const int cur = kt & 1;
        const int nxt = cur ^ 1;

        float4 pa0, pa1, pb0, pb1;
        const bool more = (kt + 1) < nkt;
        if (more) {
            pa0 = Ag[(kt + 1) * 512 + tid * 2];
            pa1 = Ag[(kt + 1) * 512 + tid * 2 + 1];
            pb0 = Bg[(kt + 1) * 512 + tid * 2];
            pb1 = Bg[(kt + 1) * 512 + tid * 2 + 1];
        }

        const float4* as = As[cur];
        const float4* bs = Bs[cur];
#pragma unroll
        for (int ks = 0; ks < 2; ++ks) {
            unsigned af[4][4];
            unsigned bf[4][2];
#pragma unroll
            for (int i = 0; i < 4; ++i) {
                float4 av = as[(ks * 8 + wm16 + i) * 32 + lane];
                af[i][0] = __float_as_uint(av.x);
                af[i][1] = __float_as_uint(av.y);
                af[i][2] = __float_as_uint(av.z);
                af[i][3] = __float_as_uint(av.w);
            }
#pragma unroll
            for (int jp = 0; jp < 2; ++jp) {
                float4 bv = bs[(ks * 8 + wjp + jp) * 32 + lane];
                bf[2 * jp][0]     = __float_as_uint(bv.x);
                bf[2 * jp][1]     = __float_as_uint(bv.y);
                bf[2 * jp + 1][0] = __float_as_uint(bv.z);
                bf[2 * jp + 1][1] = __float_as_uint(bv.w);
            }
#pragma unroll
            for (int i = 0; i < 4; ++i)
#pragma unroll
                for (int j = 0; j < 4; ++j) {
                    asm volatile(
                        "mma.sync.aligned.m16n8k8.row.col.f32.tf32.tf32.f32 "
                        "{%0,%1,%2,%3}, {%4,%5,%6,%7}, {%8,%9}, {%0,%1,%2,%3};"
                        : "+f"(acc[i][j][0]), "+f"(acc[i][j][1]),
                          "+f"(acc[i][j][2]), "+f"(acc[i][j][3])
                        : "r"(af[i][0]), "r"(af[i][1]), "r"(af[i][2]), "r"(af[i][3]),
                          "r"(bf[j][0]), "r"(bf[j][1]));
                }
        }

        if (more) {
            As[nxt][tid * 2] = pa0; As[nxt][tid * 2 + 1] = pa1;
            Bs[nxt][tid * 2] = pb0; Bs[nxt][tid * 2 + 1] = pb1;
        }
        __syncthreads();
    }

    // epilogue
#pragma unroll
    for (int i = 0; i < 4; ++i) {
        const int row0 = brow + wm + i * 16 + (lane >> 2);
#pragma unroll
        for (int j = 0; j < 4; ++j) {
            const int col = bcol + wn + j * 8 + 2 * (lane & 3);   // even
            float v0 = acc[i][j][0], v1 = acc[i][j][1];
            float v2 = acc[i][j][2], v3 = acc[i][j][3];
            if (EPI == 0) {
                *(float2*)&C[(size_t)row0 * ldc + col]       = make_float2(v0, v1);
                *(float2*)&C[(size_t)(row0 + 8) * ldc + col] = make_float2(v2, v3);
            } else if (EPI == 1) {
                const float b0 = bias[col], b1 = bias[col + 1];
                v0 += b0; v1 += b1; v2 += b0; v3 += b1;
                v0 = (v0 > 20.f) ? v0 : log1pf(__expf(v0));
                v1 = (v1 > 20.f) ? v1 : log1pf(__expf(v1));
                v2 = (v2 > 20.f) ? v2 : log1pf(__expf(v2));
                v3 = (v3 > 20.f) ? v3 : log1pf(__expf(v3));
                *(float2*)&C[(size_t)row0 * ldc + col]       = make_float2(v0, v1);
                *(float2*)&C[(size_t)(row0 + 8) * ldc + col] = make_float2(v2, v3);
            } else {
                const int ch = col >> 1;
                C[(size_t)row0 * ldc + ch]       = v0;
                C[(size_t)(row0 + 8) * ldc + ch] = v2;
                aux[(size_t)row0 * ldc + ch]       = v1 / (1.f + __expf(-v1));
                aux[(size_t)(row0 + 8) * ldc + ch] = v3 / (1.f + __expf(-v3));
            }
        }
    }
}

// ---------------- depthwise conv (SAME, k=4) + SiLU -------------------------
__global__ __launch_bounds__(256) void conv_silu_kernel(
    const float* __restrict__ ck, const float* __restrict__ cb)
{
    const int idx = blockIdx.x * blockDim.x + threadIdx.x;
    const int c = idx & (D_INNER - 1);
    const int t = (idx >> 11) & (SEQLEN - 1);
    const int b = idx >> 22;

    const float* base = g_xraw + (size_t)b * SEQLEN * D_INNER + c;

    float sum = cb[c];
#pragma unroll
    for (int j = 0; j < 4; ++j) {
        const int tt = t - 1 + j;
        if (tt >= 0 && tt < SEQLEN)
            sum = fmaf(base[(size_t)tt * D_INNER], ck[j * D_INNER + c], sum);
    }
    g_x[idx] = sum / (1.f + __expf(-sum));
}

// ---------------- skinny GEMM: x_dbl = x @ W_x ------------------------------
// cols 0..63 -> g_xdblP (fragment-packed, tf32-rounded); cols 64..95 -> g_bc.
__global__ __launch_bounds__(96) void gemm_xdbl(const float* __restrict__ Wx)
{
    __shared__ __align__(16) float As[96][16];
    const int tid = threadIdx.x;
    const int m0  = blockIdx.x * 16;

    float acc[16];
#pragma unroll
    for (int i = 0; i < 16; ++i) acc[i] = 0.f;

    for (int k0 = 0; k0 < D_INNER; k0 += 96) {
        const int chunk = min(96, D_INNER - k0);
#pragma unroll
        for (int i = 0; i < 16; ++i) {
            float v = 0.f;
            if (tid < chunk) v = g_x[(size_t)(m0 + i) * D_INNER + k0 + tid];
            As[tid][i] = v;
        }
        __syncthreads();
        for (int k = 0; k < chunk; ++k) {
            const float bv = __ldg(&Wx[(size_t)(k0 + k) * 96 + tid]);
            const float4* ap = (const float4*)&As[k][0];
#pragma unroll
            for (int q = 0; q < 4; ++q) {
                float4 a = ap[q];
                acc[4 * q + 0] = fmaf(a.x, bv, acc[4 * q + 0]);
                acc[4 * q + 1] = fmaf(a.y, bv, acc[4 * q + 1]);
                acc[4 * q + 2] = fmaf(a.z, bv, acc[4 * q + 2]);
                acc[4 * q + 3] = fmaf(a.w, bv, acc[4 * q + 3]);
            }
        }
        __syncthreads();
    }

    if (tid < DT_RANK) {
        const int kq = tid & 3, khalf = (tid >> 2) & 1, ks = (tid >> 3) & 1;
        const int kt = tid >> 4;
#pragma unroll
        for (int i = 0; i < 16; ++i) {
            const int row = m0 + i;
            size_t a = ((size_t)(row >> 7) * 4 + kt) * 2048
                     + (ks * 8 + ((row >> 4) & 7)) * 128
                     + (row & 7) * 16 + kq * 4 + ((row >> 3) & 1) + khalf * 2;
            g_xdblP[a] = f2tf_f(acc[i]);
        }
    } else {
#pragma unroll
        for (int i = 0; i < 16; ++i)
            g_bc[(size_t)(m0 + i) * 32 + tid - DT_RANK] = acc[i];
    }
}

// ---------------- selective scan (thread per (b,d,n)) -----------------------
__global__ __launch_bounds__(256) void scan_kernel(
    const float* __restrict__ A_log, const float* __restrict__ Dp)
{
    const int tid  = blockIdx.x * blockDim.x + threadIdx.x;
    const int w    = tid >> 5;
    const int lane = tid & 31;
    const int n    = lane & 15;
    const int c    = 2 * w + (lane >> 4);
    const int b    = c >> 11;
    const int d    = c & (D_INNER - 1);

    const float coef = -__expf(A_log[d * D_STATE + n]) * 1.44269504088896f;
    const float Dv   = Dp[d];

    // d-derived constants of the packed outpre address
    const size_t dterm = (size_t)(d >> 4) * 2048
                       + ((d >> 3) & 1) * 1024
                       + (d & 3) * 4 + ((d >> 2) & 1) * 2;

    float state = 0.f;
    size_t idx = (size_t)b * SEQLEN * D_INNER + d;
    size_t r32 = (size_t)b * SEQLEN * 32;

    for (int l = 0; l < SEQLEN; ++l) {
        const float delta = g_delta[idx];
        const float xv    = g_x[idx];
        const float Bv    = g_bc[r32 + n];
        const float Cv    = g_bc[r32 + 16 + n];

        const float a = ex2f(delta * coef);
        state = fmaf(a, state, delta * Bv * xv);

        float p = state * Cv;
        p += __shfl_xor_sync(0xffffffffu, p, 8);
        p += __shfl_xor_sync(0xffffffffu, p, 4);
        p += __shfl_xor_sync(0xffffffffu, p, 2);
        p += __shfl_xor_sync(0xffffffffu, p, 1);

        if (n == 0) {
            const int row = b * SEQLEN + l;
            size_t a_out = ((size_t)(row >> 7) * 128) * 2048 + dterm
                         + ((row >> 4) & 7) * 128
                         + (row & 7) * 16 + ((row >> 3) & 1);
            g_outpreP[a_out] = f2tf_f((p + xv * Dv) * g_zs[idx]);
        }

        idx += D_INNER;
        r32 += 32;
    }
}

// ---------------- launch ----------------------------------------------------
extern "C" void kernel_launch(void* const* d_in, const int* in_sizes, int n_in,
                              void* d_out, int out_size)
{
    const float* hs    = (const float*)d_in[0];
    const float* W_in  = (const float*)d_in[1];
    const float* ck    = (const float*)d_in[2];
    const float* cb    = (const float*)d_in[3];
    const float* W_x   = (const float*)d_in[4];
    const float* W_dt  = (const float*)d_in[5];
    const float* b_dt  = (const float*)d_in[6];
    const float* A_log = (const float*)d_in[7];
    const float* Dp    = (const float*)d_in[8];
    const float* W_out = (const float*)d_in[9];
    float* out = (float*)d_out;

    float *hsP, *winP, *wdtP, *woutP, *xdblP, *outpreP, *xraw, *zs, *delta;
    cudaGetSymbolAddress((void**)&hsP,     g_hsP);
    cudaGetSymbolAddress((void**)&winP,    g_winP);
    cudaGetSymbolAddress((void**)&wdtP,    g_wdtP);
    cudaGetSymbolAddress((void**)&woutP,   g_woutP);
    cudaGetSymbolAddress((void**)&xdblP,   g_xdblP);
    cudaGetSymbolAddress((void**)&outpreP, g_outpreP);
    cudaGetSymbolAddress((void**)&xraw,    g_xraw);
    cudaGetSymbolAddress((void**)&zs,      g_zs);
    cudaGetSymbolAddress((void**)&delta,   g_delta);

    // 0) pack + tf32-round all GEMM operands
    pack_a<<<BL * (D_MODEL / 16) / 256, 256>>>(hs, hsP, BL, D_MODEL);
    pack_b<<<(D_MODEL / 16) * (2 * D_INNER) / 256, 256>>>(W_in, winP, D_MODEL, 2 * D_INNER);
    pack_b<<<(DT_RANK / 16) * D_INNER / 256, 256>>>(W_dt, wdtP, DT_RANK, D_INNER);
    pack_b<<<(D_INNER / 16) * D_MODEL / 256, 256>>>(W_out, woutP, D_INNER, D_MODEL);

    // 1) xz = hs @ W_in; epilogue: x -> g_xraw, silu(z) -> g_zs
    mma_gemm_p<2><<<dim3(2 * D_INNER / 128, BL / 128), 256>>>(
        hsP, winP, xraw, nullptr, zs, D_MODEL / 16, D_INNER);

    // 2) conv + silu -> g_x
    conv_silu_kernel<<<(BL * D_INNER) / 256, 256>>>(ck, cb);

    // 3) x_dbl = x @ W_x  (dt cols packed, B/C -> g_bc)
    gemm_xdbl<<<BL / 16, 96>>>(W_x);

    // 4) delta = softplus(x_dbl[:, :64] @ W_dt + b_dt)
    mma_gemm_p<1><<<dim3(D_INNER / 128, BL / 128), 256>>>(
        xdblP, wdtP, delta, b_dt, nullptr, DT_RANK / 16, D_INNER);

    // 5) selective scan + gating -> g_outpreP (packed)
    scan_kernel<<<(BATCH * D_INNER * D_STATE) / 256, 256>>>(A_log, Dp);

    // 6) out = outpre @ W_out
    mma_gemm_p<0><<<dim3(D_MODEL / 128, BL / 128), 256>>>(
        outpreP, woutP, out, nullptr, nullptr, D_INNER / 16, D_MODEL);
}

// round 7
// speedup vs baseline: 1.3942x; 1.3942x over previous
#include <cuda_runtime.h>
#include <math.h>
#include <stdint.h>

#define D_MODEL 1024
#define D_INNER 2048
#define D_STATE 16
#define DT_RANK 64
#define BATCH   2
#define SEQLEN  2048
#define BL      (BATCH * SEQLEN)   // 4096 rows

// ---------------- scratch (static device globals; no allocation allowed) ---
__device__ float g_xraw[(size_t)BL * D_INNER];     // 32 MB  x pre-conv
__device__ float g_x[(size_t)BL * D_INNER];        // 32 MB  x after conv+silu
__device__ float g_zs[(size_t)BL * D_INNER];       // 32 MB  silu(z)
__device__ float g_xdbl[(size_t)BL * 96];          // 1.5 MB (cols 0..63 tf32-rounded)
__device__ float g_delta[(size_t)BL * D_INNER];    // 32 MB  softplus(dt)
__device__ float g_outpre[(size_t)BL * D_INNER];   // 32 MB  tf32-rounded
__device__ float g_hs_tf[(size_t)BL * D_MODEL];    // 16 MB  hs tf32-rounded
__device__ float g_winT[(size_t)(2 * D_INNER) * D_MODEL];  // 16 MB  W_in^T  [4096,1024]
__device__ float g_wdtT[(size_t)D_INNER * DT_RANK];        // 0.5 MB W_dt^T  [2048,64]
__device__ float g_woutT[(size_t)D_MODEL * D_INNER];       // 8 MB   W_out^T [1024,2048]

__device__ __forceinline__ float ex2f(float x) {
    float y; asm("ex2.approx.f32 %0, %1;" : "=f"(y) : "f"(x)); return y;
}
__device__ __forceinline__ float f2tf_f(float x) {
    unsigned r; asm("cvt.rna.tf32.f32 %0, %1;" : "=r"(r) : "f"(x));
    return __uint_as_float(r);
}

// ---------------- pre-convert fp32 -> tf32 bits -----------------------------
__global__ __launch_bounds__(256) void cvt_tf32_kernel(
    const float4* __restrict__ in, float4* __restrict__ out, int n4)
{
    for (int i = blockIdx.x * blockDim.x + threadIdx.x; i < n4;
         i += gridDim.x * blockDim.x) {
        float4 v = in[i];
        v.x = f2tf_f(v.x); v.y = f2tf_f(v.y);
        v.z = f2tf_f(v.z); v.w = f2tf_f(v.w);
        out[i] = v;
    }
}

// out[c][r] = tf32(in[r][c]); in is R x C, R,C multiples of 32.
__global__ __launch_bounds__(256) void tr_tf32_kernel(
    const float* __restrict__ in, float* __restrict__ out, int R, int C)
{
    __shared__ float t[32][33];
    const int c0 = blockIdx.x * 32, r0 = blockIdx.y * 32;
    const int tx = threadIdx.x & 31, ty = threadIdx.x >> 5;   // 32x8
#pragma unroll
    for (int i = ty; i < 32; i += 8)
        t[i][tx] = in[(size_t)(r0 + i) * C + c0 + tx];
    __syncthreads();
#pragma unroll
    for (int i = ty; i < 32; i += 8)
        out[(size_t)(c0 + i) * R + r0 + tx] = f2tf_f(t[tx][i]);
}

// ---------------- TF32 mma GEMM with ldmatrix fragment loads ----------------
// C[M,N] = A[M,K] @ Bt[N,K]^T.  A row-major [M,K], Bt row-major [N,K];
// both pre-rounded to tf32.  128x128x16 tile, 256 threads (8 warps 2x4),
// warp tile 64x32 via m16n8k8, register double-buffered SMEM, LDSM.x4 frags.
// SMEM: both operands stored [row][k] with row stride 20 floats (bank-clean).
// EPI 0: plain. 1: softplus(acc+bias[col]). 2: even->C, silu(odd)->aux.
template <int EPI>
__global__ __launch_bounds__(256) void mma_gemm_lm(
    const float* __restrict__ A, const float* __restrict__ Bt,
    float* __restrict__ C, const float* __restrict__ bias, float* __restrict__ aux,
    int M, int N, int K, int lda, int ldb, int ldc)
{
    constexpr int STR = 20;                 // floats per SMEM row
    __shared__ __align__(16) float As[2][128 * STR];
    __shared__ __align__(16) float Bs[2][128 * STR];

    const int tid  = threadIdx.x;
    const int warp = tid >> 5;
    const int lane = tid & 31;
    const int brow = blockIdx.y * 128;
    const int bcol = blockIdx.x * 128;

    const int wm = (warp >> 2) * 64;
    const int wn = (warp & 3) * 32;

    // global loader mapping: row = tid>>2 (+64 second pass), chunk = tid&3
    const int g_r = tid >> 2;
    const int g_c = (tid & 3) * 4;
    const float* Ag = A  + (size_t)(brow + g_r) * lda + g_c;
    const float* Bg = Bt + (size_t)(bcol + g_r) * ldb + g_c;

    // ldmatrix per-lane base addresses
    const int sel = lane >> 3, rin = lane & 7;
    const uint32_t sbA = (uint32_t)__cvta_generic_to_shared(&As[0][0]);
    const uint32_t sbB = (uint32_t)__cvta_generic_to_shared(&Bs[0][0]);
    // A matrices order: (m-lo,k-lo),(m-hi,k-lo),(m-lo,k-hi),(m-hi,k-hi)
    const uint32_t aBase = sbA +
        (uint32_t)(((wm + (sel & 1) * 8 + rin) * STR + (sel >> 1) * 4) * 4);
    // B matrices order: (n-blk j,k-lo),(j,k-hi),(j+1,k-lo),(j+1,k-hi)
    const uint32_t bBase = sbB +
        (uint32_t)(((wn + (sel >> 1) * 8 + rin) * STR + (sel & 1) * 4) * 4);
    constexpr uint32_t BUFSZ = 128 * STR * 4;   // bytes per buffer

    float acc[4][4][4];
#pragma unroll
    for (int i = 0; i < 4; ++i)
#pragma unroll
        for (int j = 0; j < 4; ++j)
#pragma unroll
            for (int q = 0; q < 4; ++q) acc[i][j][q] = 0.f;

    const int ntiles = K / 16;

#define STORE_TILE(buf, a0, a1, b0, b1)                                       \
    do {                                                                      \
        *(float4*)&As[buf][(g_r)      * STR + g_c] = a0;                      \
        *(float4*)&As[buf][(g_r + 64) * STR + g_c] = a1;                      \
        *(float4*)&Bs[buf][(g_r)      * STR + g_c] = b0;                      \
        *(float4*)&Bs[buf][(g_r + 64) * STR + g_c] = b1;                      \
    } while (0)

    {   // prologue
        float4 a0 = *(const float4*)(Ag);
        float4 a1 = *(const float4*)(Ag + (size_t)64 * lda);
        float4 b0 = *(const float4*)(Bg);
        float4 b1 = *(const float4*)(Bg + (size_t)64 * ldb);
        STORE_TILE(0, a0, a1, b0, b1);
    }
    __syncthreads();

    for (int kt = 0; kt < ntiles; ++kt) {
        const int cur = kt & 1;

        float4 pa0, pa1, pb0, pb1;
        const bool more = (kt + 1) < ntiles;
        if (more) {
            const float* Ak = Ag + (size_t)(kt + 1) * 16;
            const float* Bk = Bg + (size_t)(kt + 1) * 16;
            pa0 = *(const float4*)(Ak);
            pa1 = *(const float4*)(Ak + (size_t)64 * lda);
            pb0 = *(const float4*)(Bk);
            pb1 = *(const float4*)(Bk + (size_t)64 * ldb);
        }

        const uint32_t aB = aBase + cur * BUFSZ;
        const uint32_t bB = bBase + cur * BUFSZ;
#pragma unroll
        for (int ks = 0; ks < 2; ++ks) {
            unsigned af[4][4];
            unsigned bf[4][2];
#pragma unroll
            for (int i = 0; i < 4; ++i) {
                asm volatile(
                    "ldmatrix.sync.aligned.m8n8.x4.shared.b16 {%0,%1,%2,%3}, [%4];"
                    : "=r"(af[i][0]), "=r"(af[i][1]), "=r"(af[i][2]), "=r"(af[i][3])
                    : "r"(aB + i * (16 * STR * 4) + ks * 32));
            }
#pragma unroll
            for (int jp = 0; jp < 2; ++jp) {
                asm volatile(
                    "ldmatrix.sync.aligned.m8n8.x4.shared.b16 {%0,%1,%2,%3}, [%4];"
                    : "=r"(bf[2 * jp][0]), "=r"(bf[2 * jp][1]),
                      "=r"(bf[2 * jp + 1][0]), "=r"(bf[2 * jp + 1][1])
                    : "r"(bB + jp * (16 * STR * 4) + ks * 32));
            }
#pragma unroll
            for (int i = 0; i < 4; ++i)
#pragma unroll
                for (int j = 0; j < 4; ++j) {
                    asm volatile(
                        "mma.sync.aligned.m16n8k8.row.col.f32.tf32.tf32.f32 "
                        "{%0,%1,%2,%3}, {%4,%5,%6,%7}, {%8,%9}, {%0,%1,%2,%3};"
                        : "+f"(acc[i][j][0]), "+f"(acc[i][j][1]),
                          "+f"(acc[i][j][2]), "+f"(acc[i][j][3])
                        : "r"(af[i][0]), "r"(af[i][1]), "r"(af[i][2]), "r"(af[i][3]),
                          "r"(bf[j][0]), "r"(bf[j][1]));
                }
        }

        if (more) {
            STORE_TILE(cur ^ 1, pa0, pa1, pb0, pb1);
        }
        __syncthreads();
    }
#undef STORE_TILE

    // epilogue
#pragma unroll
    for (int i = 0; i < 4; ++i) {
        const int row0 = brow + wm + i * 16 + (lane >> 2);
#pragma unroll
        for (int j = 0; j < 4; ++j) {
            const int col = bcol + wn + j * 8 + 2 * (lane & 3);   // even
            float v0 = acc[i][j][0], v1 = acc[i][j][1];
            float v2 = acc[i][j][2], v3 = acc[i][j][3];
            if (EPI == 0) {
                *(float2*)&C[(size_t)row0 * ldc + col]       = make_float2(v0, v1);
                *(float2*)&C[(size_t)(row0 + 8) * ldc + col] = make_float2(v2, v3);
            } else if (EPI == 1) {
                const float b0 = bias[col], b1 = bias[col + 1];
                v0 += b0; v1 += b1; v2 += b0; v3 += b1;
                v0 = (v0 > 20.f) ? v0 : log1pf(__expf(v0));
                v1 = (v1 > 20.f) ? v1 : log1pf(__expf(v1));
                v2 = (v2 > 20.f) ? v2 : log1pf(__expf(v2));
                v3 = (v3 > 20.f) ? v3 : log1pf(__expf(v3));
                *(float2*)&C[(size_t)row0 * ldc + col]       = make_float2(v0, v1);
                *(float2*)&C[(size_t)(row0 + 8) * ldc + col] = make_float2(v2, v3);
            } else {
                const int ch = col >> 1;
                C[(size_t)row0 * ldc + ch]       = v0;
                C[(size_t)(row0 + 8) * ldc + ch] = v2;
                aux[(size_t)row0 * ldc + ch]       = v1 / (1.f + __expf(-v1));
                aux[(size_t)(row0 + 8) * ldc + ch] = v3 / (1.f + __expf(-v3));
            }
        }
    }
}

// ---------------- depthwise conv (SAME, k=4) + SiLU -------------------------
__global__ __launch_bounds__(256) void conv_silu_kernel(
    const float* __restrict__ ck, const float* __restrict__ cb)
{
    const int idx = blockIdx.x * blockDim.x + threadIdx.x;
    const int c = idx & (D_INNER - 1);
    const int t = (idx >> 11) & (SEQLEN - 1);
    const int b = idx >> 22;

    const float* base = g_xraw + (size_t)b * SEQLEN * D_INNER + c;

    float sum = cb[c];
#pragma unroll
    for (int j = 0; j < 4; ++j) {
        const int tt = t - 1 + j;
        if (tt >= 0 && tt < SEQLEN)
            sum = fmaf(base[(size_t)tt * D_INNER], ck[j * D_INNER + c], sum);
    }
    g_x[idx] = sum / (1.f + __expf(-sum));
}

// ---------------- skinny GEMM: x_dbl[BL,96] = g_x[BL,2048] @ W_x[2048,96] ---
__global__ __launch_bounds__(96) void gemm_xdbl(const float* __restrict__ Wx)
{
    __shared__ __align__(16) float As[96][16];
    const int tid = threadIdx.x;
    const int m0  = blockIdx.x * 16;

    float acc[16];
#pragma unroll
    for (int i = 0; i < 16; ++i) acc[i] = 0.f;

    for (int k0 = 0; k0 < D_INNER; k0 += 96) {
        const int chunk = min(96, D_INNER - k0);
#pragma unroll
        for (int i = 0; i < 16; ++i) {
            float v = 0.f;
            if (tid < chunk) v = g_x[(size_t)(m0 + i) * D_INNER + k0 + tid];
            As[tid][i] = v;
        }
        __syncthreads();
        for (int k = 0; k < chunk; ++k) {
            const float bv = __ldg(&Wx[(size_t)(k0 + k) * 96 + tid]);
            const float4* ap = (const float4*)&As[k][0];
#pragma unroll
            for (int q = 0; q < 4; ++q) {
                float4 a = ap[q];
                acc[4 * q + 0] = fmaf(a.x, bv, acc[4 * q + 0]);
                acc[4 * q + 1] = fmaf(a.y, bv, acc[4 * q + 1]);
                acc[4 * q + 2] = fmaf(a.z, bv, acc[4 * q + 2]);
                acc[4 * q + 3] = fmaf(a.w, bv, acc[4 * q + 3]);
            }
        }
        __syncthreads();
    }
    const bool rnd = (tid < DT_RANK);
#pragma unroll
    for (int i = 0; i < 16; ++i) {
        float v = acc[i];
        if (rnd) v = f2tf_f(v);
        g_xdbl[(size_t)(m0 + i) * 96 + tid] = v;
    }
}

// ---------------- selective scan (thread per (b,d,n)) -----------------------
__global__ __launch_bounds__(256) void scan_kernel(
    const float* __restrict__ A_log, const float* __restrict__ Dp)
{
    const int tid  = blockIdx.x * blockDim.x + threadIdx.x;
    const int w    = tid >> 5;
    const int lane = tid & 31;
    const int n    = lane & 15;
    const int c    = 2 * w + (lane >> 4);
    const int b    = c >> 11;
    const int d    = c & (D_INNER - 1);

    const float coef = -__expf(A_log[d * D_STATE + n]) * 1.44269504088896f;
    const float Dv   = Dp[d];

    float state = 0.f;
    size_t idx = (size_t)b * SEQLEN * D_INNER + d;
    int r96 = b * SEQLEN * 96;

    for (int l = 0; l < SEQLEN; ++l) {
        const float delta = g_delta[idx];
        const float xv    = g_x[idx];
        const float Bv    = g_xdbl[r96 + DT_RANK + n];
        const float Cv    = g_xdbl[r96 + DT_RANK + D_STATE + n];

        const float a = ex2f(delta * coef);
        state = fmaf(a, state, delta * Bv * xv);

        float p = state * Cv;
        p += __shfl_xor_sync(0xffffffffu, p, 8);
        p += __shfl_xor_sync(0xffffffffu, p, 4);
        p += __shfl_xor_sync(0xffffffffu, p, 2);
        p += __shfl_xor_sync(0xffffffffu, p, 1);

        if (n == 0) g_outpre[idx] = f2tf_f((p + xv * Dv) * g_zs[idx]);

        idx += D_INNER;
        r96 += 96;
    }
}

// ---------------- launch ----------------------------------------------------
extern "C" void kernel_launch(void* const* d_in, const int* in_sizes, int n_in,
                              void* d_out, int out_size)
{
    const float* hs    = (const float*)d_in[0];
    const float* W_in  = (const float*)d_in[1];
    const float* ck    = (const float*)d_in[2];
    const float* cb    = (const float*)d_in[3];
    const float* W_x   = (const float*)d_in[4];
    const float* W_dt  = (const float*)d_in[5];
    const float* b_dt  = (const float*)d_in[6];
    const float* A_log = (const float*)d_in[7];
    const float* Dp    = (const float*)d_in[8];
    const float* W_out = (const float*)d_in[9];
    float* out = (float*)d_out;

    float *xraw, *zs, *xdbl, *delta, *outpre;
    float *hs_tf, *winT, *wdtT, *woutT;
    cudaGetSymbolAddress((void**)&xraw,   g_xraw);
    cudaGetSymbolAddress((void**)&zs,     g_zs);
    cudaGetSymbolAddress((void**)&xdbl,   g_xdbl);
    cudaGetSymbolAddress((void**)&delta,  g_delta);
    cudaGetSymbolAddress((void**)&outpre, g_outpre);
    cudaGetSymbolAddress((void**)&hs_tf,  g_hs_tf);
    cudaGetSymbolAddress((void**)&winT,   g_winT);
    cudaGetSymbolAddress((void**)&wdtT,   g_wdtT);
    cudaGetSymbolAddress((void**)&woutT,  g_woutT);

    // 0) pre-round A operand; transpose+round weights to [N,K]
    cvt_tf32_kernel<<<1024, 256>>>((const float4*)hs, (float4*)hs_tf, BL * D_MODEL / 4);
    tr_tf32_kernel<<<dim3(2 * D_INNER / 32, D_MODEL / 32), 256>>>(W_in,  winT,  D_MODEL, 2 * D_INNER);
    tr_tf32_kernel<<<dim3(D_INNER / 32, DT_RANK / 32),     256>>>(W_dt,  wdtT,  DT_RANK, D_INNER);
    tr_tf32_kernel<<<dim3(D_MODEL / 32, D_INNER / 32),     256>>>(W_out, woutT, D_INNER, D_MODEL);

    // 1) xz = hs @ W_in; epilogue: x -> g_xraw, silu(z) -> g_zs
    mma_gemm_lm<2><<<dim3(2 * D_INNER / 128, BL / 128), 256>>>(
        hs_tf, winT, xraw, nullptr, zs,
        BL, 2 * D_INNER, D_MODEL, D_MODEL, D_MODEL, D_INNER);

    // 2) conv + silu -> g_x
    conv_silu_kernel<<<(BL * D_INNER) / 256, 256>>>(ck, cb);

    // 3) x_dbl = x @ W_x
    gemm_xdbl<<<BL / 16, 96>>>(W_x);

    // 4) delta = softplus(x_dbl[:, :64] @ W_dt + b_dt)
    mma_gemm_lm<1><<<dim3(D_INNER / 128, BL / 128), 256>>>(
        xdbl, wdtT, delta, b_dt, nullptr,
        BL, D_INNER, DT_RANK, 96, DT_RANK, D_INNER);

    // 5) selective scan + gating -> g_outpre (tf32-rounded)
    scan_kernel<<<(BATCH * D_INNER * D_STATE) / 256, 256>>>(A_log, Dp);

    // 6) out = outpre @ W_out
    mma_gemm_lm<0><<<dim3(D_MODEL / 128, BL / 128), 256>>>(
        outpre, woutT, out, nullptr, nullptr,
        BL, D_MODEL, D_INNER, D_INNER, D_INNER, D_MODEL);
}